// round 5
// baseline (speedup 1.0000x reference)
#include <cuda_runtime.h>
#include <math.h>

#define NN 17
#define DD 512
#define HH 8
#define MM 256
#define CIN 515

typedef unsigned long long u64;

// ---------------- f32x2 helpers ----------------
__device__ __forceinline__ void ffma2(u64& acc, u64 a, u64 b) {
    asm("fma.rn.f32x2 %0, %1, %2, %0;" : "+l"(acc) : "l"(a), "l"(b));
}
__device__ __forceinline__ void fadd2(u64& acc, u64 a) {
    asm("add.rn.f32x2 %0, %1, %0;" : "+l"(acc) : "l"(a));
}
__device__ __forceinline__ u64 dup2(float x) {
    u64 r; asm("mov.b64 %0, {%1, %1};" : "=l"(r) : "f"(x)); return r;
}
__device__ __forceinline__ u64 pack2(float x, float y) {
    u64 r; asm("mov.b64 %0, {%1, %2};" : "=l"(r) : "f"(x), "f"(y)); return r;
}
__device__ __forceinline__ float2 unpack2(u64 a) {
    float2 f; asm("mov.b64 {%0, %1}, %2;" : "=f"(f.x), "=f"(f.y) : "l"(a)); return f;
}

// ---------------- device scratch ----------------
__device__ float g_f[HH][NN][DD];          // f natural layout (for kC att@f)
__device__ u64   g_fdup[HH][NN][DD];       // f duplicated pairs (v,v) (for kB)
__device__ u64   g_hdnp[HH][MM][9];        // tanh hidden, dup-pair layout [m][(n,n+1)]
__device__ float g_out[NN * DD];           // conv accumulation (zeroed at load & each call)
__device__ int   g_ctr = 0;                // last-block counter

// ================= Kernel A: f = relu(Xs @ FC), full d-reduction in-block =================
// grid (ec=16, h=8) = 128 blocks, 512 threads = 32 d-groups x 16 e-pairs.
// dyn smem: xs2 [512][18] float2 (73728 B) + part [32][17][16] u64 (69632 B)
#define KA_SMEM (73728 + 69632)
__global__ void __launch_bounds__(512) kA(const float* __restrict__ Xs,
                                          const float* __restrict__ FC) {
    extern __shared__ __align__(16) char sm[];
    float2* xs2 = reinterpret_cast<float2*>(sm);              // [d*18 + n]
    u64*    part = reinterpret_cast<u64*>(sm + 73728);        // [(dg*17+n)*16 + ep]

    const int ec = blockIdx.x, h = blockIdx.y, tid = threadIdx.x;

    // fill duplicated Xs: xs2[d][n] = (Xs[n][d], Xs[n][d])
    for (int idx = tid; idx < NN * DD; idx += 512) {
        int n = idx >> 9, d = idx & 511;
        float v = Xs[idx];
        xs2[d * 18 + n] = make_float2(v, v);
    }
    __syncthreads();

    const int dg = tid >> 4;       // 0..31, covers d in [16dg, 16dg+16)
    const int ep = tid & 15;       // e-pair within 32-wide e-chunk

    u64 acc[18];
#pragma unroll
    for (int j = 0; j < 18; ++j) acc[j] = 0ull;

    const u64* fc = reinterpret_cast<const u64*>(FC)
                  + ((size_t)h * DD + dg * 16) * (DD / 2) + ec * 16 + ep;
    u64 buf[4];
#pragma unroll
    for (int p = 0; p < 4; ++p) buf[p] = fc[(size_t)p * 256];

#pragma unroll
    for (int i = 0; i < 16; ++i) {
        u64 w = buf[i & 3];
        if (i + 4 < 16) buf[i & 3] = fc[(size_t)(i + 4) * 256];
        const ulonglong2* row = reinterpret_cast<const ulonglong2*>(&xs2[(dg * 16 + i) * 18]);
#pragma unroll
        for (int j = 0; j < 9; ++j) {
            ulonglong2 q = row[j];
            ffma2(acc[2 * j],     q.x, w);
            ffma2(acc[2 * j + 1], q.y, w);   // j==8: pad lane, discarded
        }
    }
#pragma unroll
    for (int n = 0; n < NN; ++n)
        part[(dg * NN + n) * 16 + ep] = acc[n];
    __syncthreads();

    // reduce 32 d-groups -> relu -> write g_f (natural) + g_fdup (dup pairs)
    if (tid < NN * 16) {
        const int n = tid >> 4, p = tid & 15;
        u64 s = part[n * 16 + p];
#pragma unroll
        for (int dgi = 1; dgi < 32; ++dgi)
            fadd2(s, part[(dgi * NN + n) * 16 + p]);
        float2 v = unpack2(s);
        v.x = fmaxf(v.x, 0.f);
        v.y = fmaxf(v.y, 0.f);
        const int e = ec * 32 + 2 * p;
        *reinterpret_cast<u64*>(&g_f[h][n][e]) = pack2(v.x, v.y);
        g_fdup[h][n][e]     = dup2(v.x);
        g_fdup[h][n][e + 1] = dup2(v.y);
    }
}

// ================= Kernel B: hdn = tanh(cat @ W1 + b1), full c-reduction in-block =================
// grid (mc=8, h=8) = 64 blocks, 512 threads = 32 c-groups x 16 m-pairs.
// dyn smem: cat2 [520][18] u64 (74880 B) + part [32][17][16] u64 (69632 B) + hdn_s [32][18] f (2304 B)
#define KB_SMEM (74880 + 69632 + 2304)
__global__ void __launch_bounds__(512) kB(const float* __restrict__ ROIs,
                                          const float* __restrict__ W1,
                                          const float* __restrict__ b1) {
    extern __shared__ __align__(16) char sm[];
    u64*   cat2  = reinterpret_cast<u64*>(sm);                       // [c*18 + n]
    u64*   part  = reinterpret_cast<u64*>(sm + 74880);               // [(cg*17+n)*16 + mp]
    float* hdn_s = reinterpret_cast<float*>(sm + 74880 + 69632);     // [lm*18 + n]

    const int mc = blockIdx.x, h = blockIdx.y, tid = threadIdx.x;

    // fill duplicated cat: f part from g_fdup, coords from ROIs
    for (int idx = tid; idx < NN * DD; idx += 512) {
        int n = idx >> 9, c = idx & 511;
        cat2[c * 18 + n] = g_fdup[h][n][c];
    }
    for (int idx = tid; idx < NN * 3; idx += 512) {
        int n = idx / 3, j = idx % 3;
        cat2[(DD + j) * 18 + n] = dup2(ROIs[idx]);
    }
    if (tid < 32) hdn_s[tid * 18 + 17] = 0.f;   // pad lane for later packing
    __syncthreads();

    const int cg = tid >> 4;   // 0..31, c in [16cg, 16cg+16), cg==31 also 512..514
    const int mp = tid & 15;

    u64 acc[18];
#pragma unroll
    for (int j = 0; j < 18; ++j) acc[j] = 0ull;

    const u64* w1 = reinterpret_cast<const u64*>(W1)
                  + ((size_t)h * CIN + cg * 16) * (MM / 2) + mc * 16 + mp;
    u64 buf[4];
#pragma unroll
    for (int p = 0; p < 4; ++p) buf[p] = w1[(size_t)p * 128];

#pragma unroll
    for (int i = 0; i < 16; ++i) {
        u64 w = buf[i & 3];
        if (i + 4 < 16) buf[i & 3] = w1[(size_t)(i + 4) * 128];
        const ulonglong2* row = reinterpret_cast<const ulonglong2*>(&cat2[(cg * 16 + i) * 18]);
#pragma unroll
        for (int j = 0; j < 9; ++j) {
            ulonglong2 q = row[j];
            ffma2(acc[2 * j],     q.x, w);
            ffma2(acc[2 * j + 1], q.y, w);
        }
    }
    if (cg == 31) {   // coordinate rows c = 512..514
#pragma unroll
        for (int j3 = 0; j3 < 3; ++j3) {
            u64 w = reinterpret_cast<const u64*>(W1)[((size_t)h * CIN + DD + j3) * 128 + mc * 16 + mp];
            const ulonglong2* row = reinterpret_cast<const ulonglong2*>(&cat2[(DD + j3) * 18]);
#pragma unroll
            for (int j = 0; j < 9; ++j) {
                ulonglong2 q = row[j];
                ffma2(acc[2 * j],     q.x, w);
                ffma2(acc[2 * j + 1], q.y, w);
            }
        }
    }
#pragma unroll
    for (int n = 0; n < NN; ++n)
        part[(cg * NN + n) * 16 + mp] = acc[n];
    __syncthreads();

    // reduce + bias + tanh -> hdn_s scalar [local m][n]
    if (tid < NN * 16) {
        const int n = tid >> 4, p = tid & 15;
        u64 s = part[n * 16 + p];
#pragma unroll
        for (int cgi = 1; cgi < 32; ++cgi)
            fadd2(s, part[(cgi * NN + n) * 16 + p]);
        fadd2(s, reinterpret_cast<const u64*>(b1)[h * (MM / 2) + mc * 16 + p]);
        float2 v = unpack2(s);
        hdn_s[(2 * p) * 18 + n]     = tanhf(v.x);
        hdn_s[(2 * p + 1) * 18 + n] = tanhf(v.y);
    }
    __syncthreads();

    // transpose-pack to dup-pair layout g_hdnp[h][m][(n,n+1)]
    if (tid < 32 * 9) {
        const int lm = tid / 9, j = tid % 9;
        g_hdnp[h][mc * 32 + lm][j] = pack2(hdn_s[lm * 18 + 2 * j], hdn_s[lm * 18 + 2 * j + 1]);
    }
}

// ================= Kernel C: logits + softmax + att@f + conv-acc + last-block epilogue =================
// grid 8 (head), 512 threads
__global__ void __launch_bounds__(512) kC(const float* __restrict__ W2,
                                          const float* __restrict__ b2,
                                          const float* __restrict__ conv_w,
                                          const float* __restrict__ conv_b,
                                          const float* __restrict__ Xs,
                                          const float* __restrict__ ROIs,
                                          float* __restrict__ out, int out_size) {
    const int h = blockIdx.x, tid = threadIdx.x;

    __shared__ __align__(16) u64 hdnp_s[MM][10];     // [m][n-pair j], 10th = pad
    __shared__ float patt[16][NN][20];               // per-warp partial logits
    __shared__ float att[NN][NN];                    // logits [k][n]
    __shared__ u64  attw[NN * NN];                   // dup pairs conv_w*softmax [k*17+n]
    __shared__ int  sflag;

    // copy hdn (dup-pair layout) to smem
    for (int idx = tid; idx < MM * 9; idx += 512) {
        int m = idx / 9, j = idx % 9;
        hdnp_s[m][j] = g_hdnp[h][m][j];
    }
    __syncthreads();

    // logits = hdn @ W2: warp mq covers 16 m's, lane = k
    {
        const int mq = tid >> 5, lane = tid & 31;
        if (lane < NN) {
            u64 acc2[9];
#pragma unroll
            for (int j = 0; j < 9; ++j) acc2[j] = 0ull;
#pragma unroll
            for (int mm = 0; mm < 16; ++mm) {
                const int m = mq * 16 + mm;
                u64 w2 = dup2(W2[((size_t)h * MM + m) * NN + lane]);
                const ulonglong2* row = reinterpret_cast<const ulonglong2*>(&hdnp_s[m][0]);
#pragma unroll
                for (int j = 0; j < 4; ++j) {
                    ulonglong2 q = row[j];
                    ffma2(acc2[2 * j],     q.x, w2);
                    ffma2(acc2[2 * j + 1], q.y, w2);
                }
                ffma2(acc2[8], hdnp_s[m][8], w2);
            }
#pragma unroll
            for (int j = 0; j < 9; ++j) {
                float2 v = unpack2(acc2[j]);
                patt[mq][2 * j][lane] = v.x;
                if (2 * j + 1 < NN) patt[mq][2 * j + 1][lane] = v.y;
            }
        }
    }
    __syncthreads();

    for (int idx = tid; idx < NN * NN; idx += 512) {
        int n = idx / NN, k = idx % NN;
        float s = b2[h * NN + k];
#pragma unroll
        for (int q = 0; q < 16; ++q) s += patt[q][n][k];
        att[k][n] = s;
    }
    __syncthreads();

    // softmax over n, premultiply conv_w, store dup pairs in smem
    if (tid < NN) {
        const int k = tid;
        float mx = -1e30f;
#pragma unroll
        for (int n = 0; n < NN; ++n) mx = fmaxf(mx, att[k][n]);
        float ex[NN], sum = 0.f;
#pragma unroll
        for (int n = 0; n < NN; ++n) { ex[n] = expf(att[k][n] - mx); sum += ex[n]; }
        float scale = conv_w[h] / sum;
#pragma unroll
        for (int n = 0; n < NN; ++n) attw[k * NN + n] = dup2(ex[n] * scale);
    }
    __syncthreads();

    // h' contribution: acc[k] (pair along d) += attw[k][n] * f[n][d-pair]; atomic into g_out
    {
        const int ng = tid >> 8;          // 0: n 0..8, 1: n 9..16
        const int dp = tid & 255;         // d-pair index
        const int nlo = ng ? 9 : 0, nhi = ng ? 17 : 9;

        u64 acc[NN];
#pragma unroll
        for (int k = 0; k < NN; ++k) acc[k] = 0ull;

        for (int n = nlo; n < nhi; ++n) {
            u64 f2 = *reinterpret_cast<const u64*>(&g_f[h][n][2 * dp]);
#pragma unroll
            for (int k = 0; k < NN; ++k)
                ffma2(acc[k], attw[k * NN + n], f2);
        }
#pragma unroll
        for (int k = 0; k < NN; ++k) {
            float2 v = unpack2(acc[k]);
            atomicAdd(&g_out[k * DD + 2 * dp],     v.x);
            atomicAdd(&g_out[k * DD + 2 * dp + 1], v.y);
        }
    }

    // last-block epilogue (threadFenceReduction idiom)
    __threadfence();
    __syncthreads();
    if (tid == 0) sflag = (atomicAdd(&g_ctr, 1) == HH - 1);
    __syncthreads();
    if (sflag) {
        const float cb = conv_b[0];
        volatile float* go = g_out;
        for (int idx = tid; idx < NN * DD; idx += 512) {
            float v = go[idx];
            out[idx] = fmaxf(v + cb, 0.f) + Xs[idx];
            g_out[idx] = 0.f;                       // reset for next replay
        }
        if (tid < NN * 3 && out_size >= NN * DD + NN * 3)
            out[NN * DD + tid] = ROIs[tid];
        if (tid == 0) g_ctr = 0;                    // reset counter
    }
}

// ---------------- launch ----------------
extern "C" void kernel_launch(void* const* d_in, const int* in_sizes, int n_in,
                              void* d_out, int out_size) {
    const float *Xs = 0, *ROIs = 0, *FC = 0, *W1 = 0, *b1 = 0, *W2 = 0, *b2 = 0,
                *cw = 0, *cb = 0;
    for (int i = 0; i < n_in; ++i) {
        const float* p = (const float*)d_in[i];
        switch (in_sizes[i]) {
            case NN * DD:       Xs = p; break;
            case NN * 3:        ROIs = p; break;
            case NN * NN:       /* adj */ break;
            case HH * DD * DD:  FC = p; break;
            case HH * CIN * MM: W1 = p; break;
            case HH * MM:       b1 = p; break;
            case HH * MM * NN:  W2 = p; break;
            case HH * NN:       b2 = p; break;
            case HH:            cw = p; break;
            case 1:             cb = p; break;
            default: break;
        }
    }
    float* out = (float*)d_out;

    static bool attr_done = false;
    if (!attr_done) {
        cudaFuncSetAttribute(kA, cudaFuncAttributeMaxDynamicSharedMemorySize, KA_SMEM);
        cudaFuncSetAttribute(kB, cudaFuncAttributeMaxDynamicSharedMemorySize, KB_SMEM);
        attr_done = true;
    }

    kA<<<dim3(16, 8), 512, KA_SMEM>>>(Xs, FC);
    kB<<<dim3(8, 8), 512, KB_SMEM>>>(ROIs, W1, b1);
    kC<<<HH, 512>>>(W2, b2, cw, cb, Xs, ROIs, out, out_size);
}

// round 6
// speedup vs baseline: 1.1389x; 1.1389x over previous
#include <cuda_runtime.h>
#include <math.h>

#define NN 17
#define DD 512
#define HH 8
#define MM 256
#define CIN 515

typedef unsigned long long u64;

// ---------------- f32x2 helpers ----------------
__device__ __forceinline__ void ffma2(u64& acc, u64 a, u64 b) {
    asm("fma.rn.f32x2 %0, %1, %2, %0;" : "+l"(acc) : "l"(a), "l"(b));
}
__device__ __forceinline__ u64 dup2(float x) {
    u64 r; asm("mov.b64 %0, {%1, %1};" : "=l"(r) : "f"(x)); return r;
}
__device__ __forceinline__ float2 unpack2(u64 a) {
    float2 f; asm("mov.b64 {%0, %1}, %2;" : "=f"(f.x), "=f"(f.y) : "l"(a)); return f;
}

// ---------------- device scratch ----------------
__device__ float g_pA[16][HH][NN][DD];   // partials of Xs@FC over 16 d-chunks (32 wide)
__device__ float g_f[HH][NN][DD];        // f = relu(Xs@FC)
__device__ float g_pB[16][HH][NN][MM];   // partials of cat@W1 over 16 c-chunks (32 wide)
__device__ float g_out[NN * DD];         // conv accumulation (zero-init, reset each call)
__device__ int   g_ctr = 0;

// ================= Kernel A: partial f = Xs @ FC =================
// grid (dc=16, h=8) = 128 blocks x 256 thr. Thread owns e-pair = tid.
// All warps iterate the same dd sequence -> LDS rows are warp-uniform broadcasts.
__global__ void __launch_bounds__(256) kA(const float* __restrict__ Xs,
                                          const float* __restrict__ FC) {
    const int dc = blockIdx.x, h = blockIdx.y, tid = threadIdx.x;
    const int d0 = dc * 32;

    __shared__ __align__(16) float2 xs2[32][18];   // dup pairs [dd][n], col 17 = pad
    for (int idx = tid; idx < 32 * 18; idx += 256) {
        int dd = idx / 18, n = idx - dd * 18;
        float v = (n < NN) ? Xs[n * DD + d0 + dd] : 0.f;
        xs2[dd][n] = make_float2(v, v);
    }
    __syncthreads();

    u64 acc[NN];
#pragma unroll
    for (int n = 0; n < NN; ++n) acc[n] = 0ull;

    // u64 element (e-pair) index: h*131072 + (d0+dd)*256 + tid
    const u64* fc = reinterpret_cast<const u64*>(FC)
                  + (size_t)h * 131072 + (size_t)d0 * 256 + tid;
    u64 buf[6];
#pragma unroll
    for (int p = 0; p < 6; ++p) buf[p] = fc[(size_t)p * 256];

#pragma unroll
    for (int dd = 0; dd < 32; ++dd) {
        u64 w = buf[dd % 6];
        if (dd + 6 < 32) buf[dd % 6] = fc[(size_t)(dd + 6) * 256];
        const ulonglong2* row = reinterpret_cast<const ulonglong2*>(&xs2[dd][0]);
#pragma unroll
        for (int j = 0; j < 8; ++j) {
            ulonglong2 q = row[j];
            ffma2(acc[2 * j],     q.x, w);
            ffma2(acc[2 * j + 1], q.y, w);
        }
        ffma2(acc[16], *reinterpret_cast<const u64*>(&xs2[dd][16]), w);
    }
#pragma unroll
    for (int n = 0; n < NN; ++n)
        *reinterpret_cast<u64*>(&g_pA[dc][h][n][2 * tid]) = acc[n];
}

// ================= Kernel B: reduce f chunk + relu, partial cat @ W1 =================
// grid (cc=16, h=8) = 128 blocks x 128 thr. Thread owns m-pair = tid.
// cc==15 additionally processes the 3 coordinate rows (c = 512..514).
__global__ void __launch_bounds__(128) kB(const float* __restrict__ ROIs,
                                          const float* __restrict__ W1) {
    const int cc = blockIdx.x, h = blockIdx.y, tid = threadIdx.x;
    const int c0 = cc * 32;

    __shared__ __align__(16) float2 cat2[35][18];   // [cp][n]; rows 32..34 = coords

    for (int idx = tid; idx < NN * 32; idx += 128) {
        int n = idx >> 5, cp = idx & 31;
        float v = 0.f;
#pragma unroll
        for (int s = 0; s < 16; ++s) v += g_pA[s][h][n][c0 + cp];
        v = fmaxf(v, 0.f);
        g_f[h][n][c0 + cp] = v;
        cat2[cp][n] = make_float2(v, v);
    }
    for (int idx = tid; idx < 35; idx += 128)
        cat2[idx][17] = make_float2(0.f, 0.f);      // pad column
    if (cc == 15) {
        for (int idx = tid; idx < NN * 3; idx += 128) {
            int n = idx / 3, j = idx % 3;
            float v = ROIs[idx];
            cat2[32 + j][n] = make_float2(v, v);
        }
    }
    __syncthreads();

    u64 acc[NN];
#pragma unroll
    for (int n = 0; n < NN; ++n) acc[n] = 0ull;

    // u64 index: h*65920 + (c0+i)*128 + tid   (CIN*MM/2 = 65920, MM/2 = 128)
    const u64* w1 = reinterpret_cast<const u64*>(W1)
                  + (size_t)h * 65920 + (size_t)c0 * 128 + tid;
    u64 buf[6];
#pragma unroll
    for (int p = 0; p < 6; ++p) buf[p] = w1[(size_t)p * 128];

#pragma unroll
    for (int i = 0; i < 32; ++i) {
        u64 w = buf[i % 6];
        if (i + 6 < 32) buf[i % 6] = w1[(size_t)(i + 6) * 128];
        const ulonglong2* row = reinterpret_cast<const ulonglong2*>(&cat2[i][0]);
#pragma unroll
        for (int j = 0; j < 8; ++j) {
            ulonglong2 q = row[j];
            ffma2(acc[2 * j],     q.x, w);
            ffma2(acc[2 * j + 1], q.y, w);
        }
        ffma2(acc[16], *reinterpret_cast<const u64*>(&cat2[i][16]), w);
    }
    if (cc == 15) {
#pragma unroll
        for (int j3 = 0; j3 < 3; ++j3) {
            u64 w = reinterpret_cast<const u64*>(W1)[(size_t)h * 65920 + (size_t)(DD + j3) * 128 + tid];
            const ulonglong2* row = reinterpret_cast<const ulonglong2*>(&cat2[32 + j3][0]);
#pragma unroll
            for (int j = 0; j < 8; ++j) {
                ulonglong2 q = row[j];
                ffma2(acc[2 * j],     q.x, w);
                ffma2(acc[2 * j + 1], q.y, w);
            }
            ffma2(acc[16], *reinterpret_cast<const u64*>(&cat2[32 + j3][16]), w);
        }
    }
#pragma unroll
    for (int n = 0; n < NN; ++n)
        *reinterpret_cast<u64*>(&g_pB[cc][h][n][2 * tid]) = acc[n];
}

// ================= Kernel C: tanh + logits + softmax + att@f + epilogue =================
// grid 8 (head) x 512 thr
__global__ void __launch_bounds__(512) kC(const float* __restrict__ W2,
                                          const float* __restrict__ b1,
                                          const float* __restrict__ b2,
                                          const float* __restrict__ conv_w,
                                          const float* __restrict__ conv_b,
                                          const float* __restrict__ Xs,
                                          const float* __restrict__ ROIs,
                                          float* __restrict__ out, int out_size) {
    const int h = blockIdx.x, tid = threadIdx.x;

    __shared__ __align__(16) float hdnf[MM * 20];   // [m*20 + n] (pairs readable as u64)
    __shared__ float patt[16][NN][20];              // per-warp partial logits
    __shared__ float att[NN][NN];                   // logits [k][n]
    __shared__ u64  attw[NN * NN];                  // dup pairs conv_w*softmax [k*17+n]
    __shared__ int  sflag;

    // phase 1: reduce 16 g_pB slices (float4) + bias + tanh -> transposed hdnf
    for (int idx = tid; idx < NN * 64; idx += 512) {
        int n = idx >> 6, m4 = (idx & 63) * 4;
        float4 s = *reinterpret_cast<const float4*>(b1 + h * MM + m4);
#pragma unroll
        for (int cc = 0; cc < 16; ++cc) {
            float4 v = *reinterpret_cast<const float4*>(&g_pB[cc][h][n][m4]);
            s.x += v.x; s.y += v.y; s.z += v.z; s.w += v.w;
        }
        hdnf[(m4 + 0) * 20 + n] = tanhf(s.x);
        hdnf[(m4 + 1) * 20 + n] = tanhf(s.y);
        hdnf[(m4 + 2) * 20 + n] = tanhf(s.z);
        hdnf[(m4 + 3) * 20 + n] = tanhf(s.w);
    }
    if (tid < MM) hdnf[tid * 20 + 17] = 0.f;   // pad lane
    __syncthreads();

    // phase 2: logits = hdn @ W2; warp mq covers 16 m's, lane = k
    {
        const int mq = tid >> 5, lane = tid & 31;
        if (lane < NN) {
            u64 acc2[9];
#pragma unroll
            for (int j = 0; j < 9; ++j) acc2[j] = 0ull;
#pragma unroll
            for (int mm = 0; mm < 16; ++mm) {
                const int m = mq * 16 + mm;
                u64 w2 = dup2(W2[((size_t)h * MM + m) * NN + lane]);
                const ulonglong2* row = reinterpret_cast<const ulonglong2*>(&hdnf[m * 20]);
#pragma unroll
                for (int j = 0; j < 4; ++j) {
                    ulonglong2 q = row[j];
                    ffma2(acc2[2 * j],     q.x, w2);
                    ffma2(acc2[2 * j + 1], q.y, w2);
                }
                ffma2(acc2[8], *reinterpret_cast<const u64*>(&hdnf[m * 20 + 16]), w2);
            }
#pragma unroll
            for (int j = 0; j < 9; ++j) {
                float2 v = unpack2(acc2[j]);
                patt[mq][2 * j][lane] = v.x;
                if (2 * j + 1 < NN) patt[mq][2 * j + 1][lane] = v.y;
            }
        }
    }
    __syncthreads();

    for (int idx = tid; idx < NN * NN; idx += 512) {
        int n = idx / NN, k = idx % NN;
        float s = b2[h * NN + k];
#pragma unroll
        for (int q = 0; q < 16; ++q) s += patt[q][n][k];
        att[k][n] = s;
    }
    __syncthreads();

    // phase 3: softmax over n, premultiply conv_w
    if (tid < NN) {
        const int k = tid;
        float mx = -1e30f;
#pragma unroll
        for (int n = 0; n < NN; ++n) mx = fmaxf(mx, att[k][n]);
        float ex[NN], sum = 0.f;
#pragma unroll
        for (int n = 0; n < NN; ++n) { ex[n] = expf(att[k][n] - mx); sum += ex[n]; }
        float scale = conv_w[h] / sum;
#pragma unroll
        for (int n = 0; n < NN; ++n) attw[k * NN + n] = dup2(ex[n] * scale);
    }
    __syncthreads();

    // phase 4: this head's conv contribution -> atomic accumulate into g_out
    {
        const int ng  = tid >> 8;        // 0: n 0..8, 1: n 9..16
        const int dp  = tid & 255;       // d-pair index
        const int nlo = ng ? 9 : 0, nhi = ng ? 17 : 9;

        u64 acc[NN];
#pragma unroll
        for (int k = 0; k < NN; ++k) acc[k] = 0ull;

        for (int n = nlo; n < nhi; ++n) {
            u64 f2 = *reinterpret_cast<const u64*>(&g_f[h][n][2 * dp]);
#pragma unroll
            for (int k = 0; k < NN; ++k)
                ffma2(acc[k], attw[k * NN + n], f2);
        }
#pragma unroll
        for (int k = 0; k < NN; ++k) {
            float2 v = unpack2(acc[k]);
            atomicAdd(&g_out[k * DD + 2 * dp],     v.x);
            atomicAdd(&g_out[k * DD + 2 * dp + 1], v.y);
        }
    }

    // last-block epilogue
    __threadfence();
    __syncthreads();
    if (tid == 0) sflag = (atomicAdd(&g_ctr, 1) == HH - 1);
    __syncthreads();
    if (sflag) {
        const float cb = conv_b[0];
        volatile float* go = g_out;
        for (int idx = tid; idx < NN * DD; idx += 512) {
            float v = go[idx];
            out[idx] = fmaxf(v + cb, 0.f) + Xs[idx];
            g_out[idx] = 0.f;                       // reset for next replay
        }
        if (tid < NN * 3 && out_size >= NN * DD + NN * 3)
            out[NN * DD + tid] = ROIs[tid];
        if (tid == 0) g_ctr = 0;
    }
}

// ---------------- launch ----------------
extern "C" void kernel_launch(void* const* d_in, const int* in_sizes, int n_in,
                              void* d_out, int out_size) {
    const float *Xs = 0, *ROIs = 0, *FC = 0, *W1 = 0, *b1 = 0, *W2 = 0, *b2 = 0,
                *cw = 0, *cb = 0;
    for (int i = 0; i < n_in; ++i) {
        const float* p = (const float*)d_in[i];
        switch (in_sizes[i]) {
            case NN * DD:       Xs = p; break;
            case NN * 3:        ROIs = p; break;
            case NN * NN:       /* adj */ break;
            case HH * DD * DD:  FC = p; break;
            case HH * CIN * MM: W1 = p; break;
            case HH * MM:       b1 = p; break;
            case HH * MM * NN:  W2 = p; break;
            case HH * NN:       b2 = p; break;
            case HH:            cw = p; break;
            case 1:             cb = p; break;
            default: break;
        }
    }
    float* out = (float*)d_out;

    kA<<<dim3(16, 8), 256>>>(Xs, FC);
    kB<<<dim3(16, 8), 128>>>(ROIs, W1);
    kC<<<HH, 512>>>(W2, b1, b2, cw, cb, Xs, ROIs, out, out_size);
}